// round 10
// baseline (speedup 1.0000x reference)
#include <cuda_runtime.h>
#include <cuda_bf16.h>
#include <cuda_fp16.h>
#include <cstdint>

#define HW 512
#define NB 8
#define NC 32

// R scratch: 30 planes [j*3+ky][b][y][x] fp16 = 126 MB
__device__ __half g_R[(size_t)30 * NB * HW * HW];

// ---------------- smem layout (pass 1) ----------------
// Tile = 256 output pixels, computed over 288-pixel range (16-px halo).
// Y tile : halfs, [96][296] at byte 0   (56832 B)
// A tile : halfs, [288][40] at byte 0   (23040 B, overlaps Y; all x-fragment
//          reads complete before Y is written). Row = 80 B: 4 data granules
//          of 16 B + 1 pad granule. Granule SWIZZLE: octet `oct` of row r
//          lives at slot (oct + (r>>3)) & 3   -> STS.128 at bank floor.
// W tile : halfs, [96][32]  at byte 56832 (6144 B)
#define MTILE 288
#define Y_STRIDE 296
#define W_OFF 56832
#define SMEM_SIZE 62976

__device__ __forceinline__ uint32_t smem_to_u32(const void* smem_ptr) {
    uint32_t addr;
    asm("{ .reg .u64 tmp; cvta.to.shared.u64 tmp, %1; cvt.u32.u64 %0, tmp; }"
        : "=r"(addr) : "l"(smem_ptr));
    return addr;
}

__device__ __forceinline__ void ldmatrix_x4(
    uint32_t& r0, uint32_t& r1, uint32_t& r2, uint32_t& r3, uint32_t addr)
{
    asm volatile(
        "ldmatrix.sync.aligned.m8n8.x4.shared.b16 {%0,%1,%2,%3}, [%4];"
        : "=r"(r0), "=r"(r1), "=r"(r2), "=r"(r3) : "r"(addr));
}

__device__ __forceinline__ void mma16816(
    float* d, const uint32_t* a, uint32_t b0, uint32_t b1)
{
    asm volatile(
        "mma.sync.aligned.m16n8k16.row.col.f32.f16.f16.f32 "
        "{%0,%1,%2,%3}, {%4,%5,%6,%7}, {%8,%9}, {%0,%1,%2,%3};"
        : "+f"(d[0]), "+f"(d[1]), "+f"(d[2]), "+f"(d[3])
        : "r"(a[0]), "r"(a[1]), "r"(a[2]), "r"(a[3]), "r"(b0), "r"(b1));
}

// Extract 4 consecutive uint32 (8 halves) starting at half-offset e (0..7)
// from 16 aligned halves held in w[0..7]. e must be warp-uniform (it is).
__device__ __forceinline__ void extract4of8(
    const uint32_t* w, int e, uint32_t* r)
{
    int i = e >> 1;
    if (e & 1) {
        #pragma unroll
        for (int k = 0; k < 4; k++)
            r[k] = __funnelshift_r(w[i + k], w[i + k + 1], 16);
    } else {
        #pragma unroll
        for (int k = 0; k < 4; k++)
            r[k] = w[i + k];
    }
}

// =====================================================================
// Pass 1: one CTA per 256-pixel half-row. 288 threads = 9 warps, occ 3.
//   GEMM: D[n][m] = sum_k W[n][k] * x[m][k]  over 288-pixel halo range
//   Horizontal (kx) fold -> R[(j,ky)] fp16 for the 256 owned pixels.
//   Passthrough copy of x (channels 0..31) fused into the A fill.
// =====================================================================
__global__ void __launch_bounds__(288, 3)
msd_pass1(const float* __restrict__ x, const float* __restrict__ W,
          float* __restrict__ out)
{
    extern __shared__ char smem[];
    const uint32_t smem_base = smem_to_u32(smem);
    const int tid = threadIdx.x;
    const int wid = tid >> 5;
    const int lid = tid & 31;
    const int P0 = blockIdx.x * 256;      // first owned pixel
    const int y = blockIdx.y;
    const int b = blockIdx.z;

    __half* ws = reinterpret_cast<__half*>(smem + W_OFF);
    __half* Ys = reinterpret_cast<__half*>(smem);

    // ---- fill W operand: w_s[n][c], n = j*9+ky*3+kx ----
    for (int idx = tid; idx < 96 * 32; idx += 288) {
        int n = idx >> 5, c = idx & 31;
        float w = 0.0f;
        if (n < 90) {
            int j = n / 9, rem = n - j * 9;
            int ky = rem / 3, kx = rem - ky * 3;
            w = W[((j * 32 + c) * 3 + ky) * 3 + kx];
        }
        ws[n * 32 + c] = __float2half(w);
    }

    // ---- fill A: thread = (pixel quad, channel octet); LDG/STG.128,
    //      swizzled STS.128 (bank floor); streaming stores ----
    const size_t xbase = (size_t)b * NC * HW * HW + (size_t)y * HW;
    const size_t obase = (size_t)b * 42 * HW * HW + (size_t)y * HW;
    {
        const int quad = tid % 72;         // 72 quads x 4 px = 288 px
        const int oct  = tid / 72;         // 4 octets x 8 ch = 32 ch
        const int lp0  = quad * 4;         // local pixel base
        const int gp0  = P0 - 16 + lp0;    // global pixel base (quad-aligned)
        const bool inimg = (gp0 >= 0) && (gp0 < HW);
        const bool owned = (lp0 >= 16) && (lp0 < 272);
        const int slot = (oct + (lp0 >> 3)) & 3;   // swizzled granule
        float v[8][4];
        #pragma unroll
        for (int c8 = 0; c8 < 8; c8++) {
            int c = oct * 8 + c8;
            float4 f = inimg
                ? *reinterpret_cast<const float4*>(
                      &x[xbase + (size_t)c * (HW * HW) + gp0])
                : make_float4(0.f, 0.f, 0.f, 0.f);
            v[c8][0] = f.x; v[c8][1] = f.y; v[c8][2] = f.z; v[c8][3] = f.w;
        }
        if (owned) {
            #pragma unroll
            for (int c8 = 0; c8 < 8; c8++) {
                int c = oct * 8 + c8;
                __stcs(reinterpret_cast<float4*>(
                           &out[obase + (size_t)c * (HW * HW) + gp0]),
                       make_float4(v[c8][0], v[c8][1], v[c8][2], v[c8][3]));
            }
        }
        #pragma unroll
        for (int i = 0; i < 4; i++) {
            __half2 h0 = __floats2half2_rn(v[0][i], v[1][i]);
            __half2 h1 = __floats2half2_rn(v[2][i], v[3][i]);
            __half2 h2 = __floats2half2_rn(v[4][i], v[5][i]);
            __half2 h3 = __floats2half2_rn(v[6][i], v[7][i]);
            *reinterpret_cast<uint4*>(smem + (lp0 + i) * 80 + slot * 16) =
                make_uint4(*reinterpret_cast<uint32_t*>(&h0),
                           *reinterpret_cast<uint32_t*>(&h1),
                           *reinterpret_cast<uint32_t*>(&h2),
                           *reinterpret_cast<uint32_t*>(&h3));
        }
    }
    __syncthreads();

    // ---- preload x (B operand) fragments: swizzle-aware LDS.32 pairs ----
    const int mb = wid * 32;
    const int g = lid >> 2, t = lid & 3;
    uint32_t bx[4][2][2];
    #pragma unroll
    for (int m8 = 0; m8 < 4; m8++)
        #pragma unroll
        for (int kh = 0; kh < 2; kh++) {
            int row = mb + m8 * 8 + g;
            int r3 = row >> 3;
            int gr0 = (2 * kh + r3) & 3;
            int gr1 = (2 * kh + 1 + r3) & 3;
            bx[m8][kh][0] = *reinterpret_cast<const uint32_t*>(
                smem + row * 80 + gr0 * 16 + 4 * t);
            bx[m8][kh][1] = *reinterpret_cast<const uint32_t*>(
                smem + row * 80 + gr1 * 16 + 4 * t);
        }
    __syncthreads();   // all x reads done -> Y may overwrite A region

    // ---- MMA: loop 6 n-tiles of 16; scatter half2 (conflict-free) ----
    const int r8 = lid & 7, t8 = lid >> 3;
    #pragma unroll
    for (int nt = 0; nt < 6; nt++) {
        const int n0 = nt * 16;
        uint32_t aw[2][4];
        #pragma unroll
        for (int kh = 0; kh < 2; kh++) {
            int row = n0 + r8 + (t8 & 1) * 8;
            int col = kh * 16 + (t8 >> 1) * 8;
            ldmatrix_x4(aw[kh][0], aw[kh][1], aw[kh][2], aw[kh][3],
                        smem_base + W_OFF + row * 64 + col * 2);
        }
        float acc[4][4];
        #pragma unroll
        for (int m8 = 0; m8 < 4; m8++) {
            #pragma unroll
            for (int i = 0; i < 4; i++) acc[m8][i] = 0.0f;
            #pragma unroll
            for (int kh = 0; kh < 2; kh++)
                mma16816(acc[m8], aw[kh], bx[m8][kh][0], bx[m8][kh][1]);
        }
        #pragma unroll
        for (int m8 = 0; m8 < 4; m8++) {
            int mcol = mb + m8 * 8 + 2 * t;
            __half2 lo = __floats2half2_rn(acc[m8][0], acc[m8][1]);
            __half2 hi = __floats2half2_rn(acc[m8][2], acc[m8][3]);
            *reinterpret_cast<__half2*>(&Ys[(n0 + g) * Y_STRIDE + mcol]) = lo;
            *reinterpret_cast<__half2*>(&Ys[(n0 + g + 8) * Y_STRIDE + mcol]) = hi;
        }
    }
    __syncthreads();

    // ---- horizontal (kx) fold -> R fp16; 8 px/task, LDS.128 taps ----
    // 30 planes x 32 octs = 960 tasks; all lanes of a warp share one plane
    // (32 tasks per plane), so extraction offsets are warp-uniform.
    const size_t rowbase = ((size_t)b * HW + y) * HW;
    for (int idx = tid; idx < 30 * 32; idx += 288) {
        int p = idx >> 5;          // plane 0..29  (n = 3p)
        int q = idx & 31;          // 8-px group within owned 256 pixels
        int j = p / 3;
        int n = 3 * p;
        int d = j + 1;
        int lm = q * 8 + 16;       // local pixel of group start (lm % 8 == 0)

        // center: 8 halves, 16B aligned
        uint4 cc = *reinterpret_cast<const uint4*>(&Ys[(n + 1) * Y_STRIDE + lm]);
        // left taps: halves [lm-d, lm-d+8)
        int el = (-d) & 7;
        int baseL = lm - d - el;
        uint32_t wl[8], lv[4];
        {
            uint4 v0 = *reinterpret_cast<const uint4*>(&Ys[n * Y_STRIDE + baseL]);
            uint4 v1 = *reinterpret_cast<const uint4*>(&Ys[n * Y_STRIDE + baseL + 8]);
            wl[0] = v0.x; wl[1] = v0.y; wl[2] = v0.z; wl[3] = v0.w;
            wl[4] = v1.x; wl[5] = v1.y; wl[6] = v1.z; wl[7] = v1.w;
        }
        extract4of8(wl, el, lv);
        // right taps: halves [lm+d, lm+d+8)
        int er = d & 7;
        int baseR = lm + d - er;
        uint32_t wr[8], rv[4];
        {
            uint4 v0 = *reinterpret_cast<const uint4*>(&Ys[(n + 2) * Y_STRIDE + baseR]);
            uint4 v1 = *reinterpret_cast<const uint4*>(&Ys[(n + 2) * Y_STRIDE + baseR + 8]);
            wr[0] = v0.x; wr[1] = v0.y; wr[2] = v0.z; wr[3] = v0.w;
            wr[4] = v1.x; wr[5] = v1.y; wr[6] = v1.z; wr[7] = v1.w;
        }
        extract4of8(wr, er, rv);

        const uint32_t* cp = reinterpret_cast<const uint32_t*>(&cc);
        uint4 ov;
        uint32_t* op = reinterpret_cast<uint32_t*>(&ov);
        #pragma unroll
        for (int k = 0; k < 4; k++) {
            __half2 s = __hadd2(__hadd2(
                *reinterpret_cast<const __half2*>(&cp[k]),
                *reinterpret_cast<__half2*>(&lv[k])),
                *reinterpret_cast<__half2*>(&rv[k]));
            op[k] = *reinterpret_cast<uint32_t*>(&s);
        }
        __stcs(reinterpret_cast<uint4*>(
                   g_R + (size_t)p * ((size_t)NB * HW * HW) + rowbase + P0 + q * 8),
               ov);
    }
}

// =====================================================================
// Pass 2: vertical (ky) fold + bias. 4 pixels per thread, float4 store.
// =====================================================================
__global__ void __launch_bounds__(256)
msd_pass2(const float* __restrict__ bias, float* __restrict__ out)
{
    int idx4 = blockIdx.x * 256 + threadIdx.x;
    int x4 = idx4 & 127;
    int y  = (idx4 >> 7) & 511;
    int t  = idx4 >> 16;
    int j  = t % 10;
    int b  = t / 10;
    int d  = j + 1;
    float bj = __ldg(bias + j);
    float a0 = bj, a1 = bj, a2 = bj, a3 = bj;
    #pragma unroll
    for (int ky = 0; ky < 3; ky++) {
        int y2 = y + (ky - 1) * d;
        if (y2 < 0 || y2 >= HW) continue;
        uint2 rv = __ldcs(reinterpret_cast<const uint2*>(
            g_R + (size_t)(j * 3 + ky) * ((size_t)NB * HW * HW)
                + ((size_t)b * HW + y2) * HW + (size_t)x4 * 4));
        float2 f0 = __half22float2(*reinterpret_cast<__half2*>(&rv.x));
        float2 f1 = __half22float2(*reinterpret_cast<__half2*>(&rv.y));
        a0 += f0.x; a1 += f0.y; a2 += f1.x; a3 += f1.y;
    }
    __stcs(reinterpret_cast<float4*>(
               out + ((size_t)(b * 42 + 32 + j) * HW + y) * HW + (size_t)x4 * 4),
           make_float4(a0, a1, a2, a3));
}

// =====================================================================
extern "C" void kernel_launch(void* const* d_in, const int* in_sizes, int n_in,
                              void* d_out, int out_size)
{
    const float* x = nullptr;
    const float* W = nullptr;
    const float* bias = nullptr;
    for (int i = 0; i < n_in; i++) {
        if (in_sizes[i] == 8 * 32 * 512 * 512) x    = (const float*)d_in[i];
        else if (in_sizes[i] == 2880)          W    = (const float*)d_in[i];
        else if (in_sizes[i] == 10)            bias = (const float*)d_in[i];
    }
    float* out = (float*)d_out;

    cudaFuncSetAttribute(msd_pass1,
                         cudaFuncAttributeMaxDynamicSharedMemorySize, SMEM_SIZE);

    dim3 g1(2, HW, NB);
    msd_pass1<<<g1, MTILE, SMEM_SIZE>>>(x, W, out);

    int n4 = NB * 10 * HW * HW / 4;          // 5,242,880 quads
    msd_pass2<<<n4 / 256, 256>>>(bias, out);
}

// round 11
// speedup vs baseline: 1.2127x; 1.2127x over previous
#include <cuda_runtime.h>
#include <cuda_bf16.h>
#include <cuda_fp16.h>
#include <cstdint>

#define HW 512
#define NB 8
#define NC 32

// R scratch: 30 planes [j*3+ky][b][y][x] fp16 = 126 MB
__device__ __half g_R[(size_t)30 * NB * HW * HW];

// ---------------- smem layout (pass 1) ----------------
// Tile = 256 output pixels, computed over 288-pixel range (16-px halo).
// Y tile : halfs, [96][296] at byte 0   (56832 B)
// A tile : halfs, [288][40] at byte 0   (23040 B, overlaps Y; all x-fragment
//          reads complete before Y is written). Row = 80 B: 4 data granules
//          of 16 B + 1 pad granule. Granule SWIZZLE: octet `oct` of row r
//          lives at slot (oct + (r>>3)) & 3   -> STS.128 at bank floor.
// W tile : halfs, [96][32]  at byte 56832 (6144 B)
#define MTILE 288
#define Y_STRIDE 296
#define W_OFF 56832
#define SMEM_SIZE 62976

__device__ __forceinline__ uint32_t smem_to_u32(const void* smem_ptr) {
    uint32_t addr;
    asm("{ .reg .u64 tmp; cvta.to.shared.u64 tmp, %1; cvt.u32.u64 %0, tmp; }"
        : "=r"(addr) : "l"(smem_ptr));
    return addr;
}

__device__ __forceinline__ void ldmatrix_x4(
    uint32_t& r0, uint32_t& r1, uint32_t& r2, uint32_t& r3, uint32_t addr)
{
    asm volatile(
        "ldmatrix.sync.aligned.m8n8.x4.shared.b16 {%0,%1,%2,%3}, [%4];"
        : "=r"(r0), "=r"(r1), "=r"(r2), "=r"(r3) : "r"(addr));
}

__device__ __forceinline__ void mma16816(
    float* d, const uint32_t* a, uint32_t b0, uint32_t b1)
{
    asm volatile(
        "mma.sync.aligned.m16n8k16.row.col.f32.f16.f16.f32 "
        "{%0,%1,%2,%3}, {%4,%5,%6,%7}, {%8,%9}, {%0,%1,%2,%3};"
        : "+f"(d[0]), "+f"(d[1]), "+f"(d[2]), "+f"(d[3])
        : "r"(a[0]), "r"(a[1]), "r"(a[2]), "r"(a[3]), "r"(b0), "r"(b1));
}

// Extract 4 consecutive halves starting at offset e (0..3) from 8 aligned
// halves held in w[0..3]. e must be warp-uniform (it is: e = (+-d)&3).
__device__ __forceinline__ void extract4(
    const uint32_t* w, int e, uint32_t& r0, uint32_t& r1)
{
    uint32_t a0 = (e & 2) ? w[1] : w[0];
    uint32_t a1 = (e & 2) ? w[2] : w[1];
    uint32_t a2 = (e & 2) ? w[3] : w[2];
    if (e & 1) {
        r0 = __funnelshift_r(a0, a1, 16);
        r1 = __funnelshift_r(a1, a2, 16);
    } else {
        r0 = a0;
        r1 = a1;
    }
}

// =====================================================================
// Pass 1: one CTA per 256-pixel half-row. 288 threads = 9 warps, occ 3.
//   GEMM: D[n][m] = sum_k W[n][k] * x[m][k]  over 288-pixel halo range
//   Horizontal (kx) fold -> R[(j,ky)] fp16 for the 256 owned pixels.
//   Passthrough copy of x (channels 0..31) fused into the A fill.
// =====================================================================
__global__ void __launch_bounds__(288, 3)
msd_pass1(const float* __restrict__ x, const float* __restrict__ W,
          float* __restrict__ out)
{
    extern __shared__ char smem[];
    const uint32_t smem_base = smem_to_u32(smem);
    const int tid = threadIdx.x;
    const int wid = tid >> 5;
    const int lid = tid & 31;
    const int P0 = blockIdx.x * 256;      // first owned pixel
    const int y = blockIdx.y;
    const int b = blockIdx.z;

    __half* ws = reinterpret_cast<__half*>(smem + W_OFF);
    __half* Ys = reinterpret_cast<__half*>(smem);

    // ---- fill W operand: w_s[n][c], n = j*9+ky*3+kx ----
    for (int idx = tid; idx < 96 * 32; idx += 288) {
        int n = idx >> 5, c = idx & 31;
        float w = 0.0f;
        if (n < 90) {
            int j = n / 9, rem = n - j * 9;
            int ky = rem / 3, kx = rem - ky * 3;
            w = W[((j * 32 + c) * 3 + ky) * 3 + kx];
        }
        ws[n * 32 + c] = __float2half(w);
    }

    // ---- fill A: thread = (pixel quad, channel octet); LDG/STG.128,
    //      swizzled STS.128 (bank floor); streaming stores ----
    const size_t xbase = (size_t)b * NC * HW * HW + (size_t)y * HW;
    const size_t obase = (size_t)b * 42 * HW * HW + (size_t)y * HW;
    {
        const int quad = tid % 72;         // 72 quads x 4 px = 288 px
        const int oct  = tid / 72;         // 4 octets x 8 ch = 32 ch
        const int lp0  = quad * 4;         // local pixel base
        const int gp0  = P0 - 16 + lp0;    // global pixel base (quad-aligned)
        const bool inimg = (gp0 >= 0) && (gp0 < HW);
        const bool owned = (lp0 >= 16) && (lp0 < 272);
        const int slot = (oct + (lp0 >> 3)) & 3;   // swizzled granule
        float v[8][4];
        #pragma unroll
        for (int c8 = 0; c8 < 8; c8++) {
            int c = oct * 8 + c8;
            float4 f = inimg
                ? *reinterpret_cast<const float4*>(
                      &x[xbase + (size_t)c * (HW * HW) + gp0])
                : make_float4(0.f, 0.f, 0.f, 0.f);
            v[c8][0] = f.x; v[c8][1] = f.y; v[c8][2] = f.z; v[c8][3] = f.w;
        }
        if (owned) {
            #pragma unroll
            for (int c8 = 0; c8 < 8; c8++) {
                int c = oct * 8 + c8;
                __stcs(reinterpret_cast<float4*>(
                           &out[obase + (size_t)c * (HW * HW) + gp0]),
                       make_float4(v[c8][0], v[c8][1], v[c8][2], v[c8][3]));
            }
        }
        #pragma unroll
        for (int i = 0; i < 4; i++) {
            __half2 h0 = __floats2half2_rn(v[0][i], v[1][i]);
            __half2 h1 = __floats2half2_rn(v[2][i], v[3][i]);
            __half2 h2 = __floats2half2_rn(v[4][i], v[5][i]);
            __half2 h3 = __floats2half2_rn(v[6][i], v[7][i]);
            *reinterpret_cast<uint4*>(smem + (lp0 + i) * 80 + slot * 16) =
                make_uint4(*reinterpret_cast<uint32_t*>(&h0),
                           *reinterpret_cast<uint32_t*>(&h1),
                           *reinterpret_cast<uint32_t*>(&h2),
                           *reinterpret_cast<uint32_t*>(&h3));
        }
    }
    __syncthreads();

    // ---- preload x (B operand) fragments: swizzle-aware LDS.32 pairs ----
    const int mb = wid * 32;
    const int g = lid >> 2, t = lid & 3;
    uint32_t bx[4][2][2];
    #pragma unroll
    for (int m8 = 0; m8 < 4; m8++)
        #pragma unroll
        for (int kh = 0; kh < 2; kh++) {
            int row = mb + m8 * 8 + g;
            int r3 = row >> 3;
            int gr0 = (2 * kh + r3) & 3;
            int gr1 = (2 * kh + 1 + r3) & 3;
            bx[m8][kh][0] = *reinterpret_cast<const uint32_t*>(
                smem + row * 80 + gr0 * 16 + 4 * t);
            bx[m8][kh][1] = *reinterpret_cast<const uint32_t*>(
                smem + row * 80 + gr1 * 16 + 4 * t);
        }
    __syncthreads();   // all x reads done -> Y may overwrite A region

    // ---- MMA: loop 6 n-tiles of 16; scatter half2 (conflict-free) ----
    const int r8 = lid & 7, t8 = lid >> 3;
    #pragma unroll
    for (int nt = 0; nt < 6; nt++) {
        const int n0 = nt * 16;
        uint32_t aw[2][4];
        #pragma unroll
        for (int kh = 0; kh < 2; kh++) {
            int row = n0 + r8 + (t8 & 1) * 8;
            int col = kh * 16 + (t8 >> 1) * 8;
            ldmatrix_x4(aw[kh][0], aw[kh][1], aw[kh][2], aw[kh][3],
                        smem_base + W_OFF + row * 64 + col * 2);
        }
        float acc[4][4];
        #pragma unroll
        for (int m8 = 0; m8 < 4; m8++) {
            #pragma unroll
            for (int i = 0; i < 4; i++) acc[m8][i] = 0.0f;
            #pragma unroll
            for (int kh = 0; kh < 2; kh++)
                mma16816(acc[m8], aw[kh], bx[m8][kh][0], bx[m8][kh][1]);
        }
        #pragma unroll
        for (int m8 = 0; m8 < 4; m8++) {
            int mcol = mb + m8 * 8 + 2 * t;
            __half2 lo = __floats2half2_rn(acc[m8][0], acc[m8][1]);
            __half2 hi = __floats2half2_rn(acc[m8][2], acc[m8][3]);
            *reinterpret_cast<__half2*>(&Ys[(n0 + g) * Y_STRIDE + mcol]) = lo;
            *reinterpret_cast<__half2*>(&Ys[(n0 + g + 8) * Y_STRIDE + mcol]) = hi;
        }
    }
    __syncthreads();

    // ---- horizontal (kx) fold -> R fp16; vector taps, HADD2 sums ----
    const size_t rowbase = ((size_t)b * HW + y) * HW;
    for (int idx = tid; idx < 30 * 64; idx += 288) {
        int p = idx >> 6;          // plane 0..29  (n = 3p)
        int q = idx & 63;          // quad within owned 256 pixels
        int j = p / 3;
        int n = 3 * p;
        int d = j + 1;
        int lm = q * 4 + 16;       // local pixel of quad start (lm % 4 == 0)

        uint2 cc = *reinterpret_cast<const uint2*>(&Ys[(n + 1) * Y_STRIDE + lm]);
        int el = (-d) & 3;
        int baseL = lm - d - el;
        uint32_t wl[4];
        {
            uint2 v0 = *reinterpret_cast<const uint2*>(&Ys[n * Y_STRIDE + baseL]);
            uint2 v1 = *reinterpret_cast<const uint2*>(&Ys[n * Y_STRIDE + baseL + 4]);
            wl[0] = v0.x; wl[1] = v0.y; wl[2] = v1.x; wl[3] = v1.y;
        }
        uint32_t l0, l1;
        extract4(wl, el, l0, l1);
        int er = d & 3;
        int baseR = lm + d - er;
        uint32_t wr[4];
        {
            uint2 v0 = *reinterpret_cast<const uint2*>(&Ys[(n + 2) * Y_STRIDE + baseR]);
            uint2 v1 = *reinterpret_cast<const uint2*>(&Ys[(n + 2) * Y_STRIDE + baseR + 4]);
            wr[0] = v0.x; wr[1] = v0.y; wr[2] = v1.x; wr[3] = v1.y;
        }
        uint32_t rr0, rr1;
        extract4(wr, er, rr0, rr1);

        __half2 o01 = __hadd2(__hadd2(*reinterpret_cast<__half2*>(&cc.x),
                                      *reinterpret_cast<__half2*>(&l0)),
                              *reinterpret_cast<__half2*>(&rr0));
        __half2 o23 = __hadd2(__hadd2(*reinterpret_cast<__half2*>(&cc.y),
                                      *reinterpret_cast<__half2*>(&l1)),
                              *reinterpret_cast<__half2*>(&rr1));
        uint2 ov = make_uint2(*reinterpret_cast<uint32_t*>(&o01),
                              *reinterpret_cast<uint32_t*>(&o23));
        __stcs(reinterpret_cast<uint2*>(
                   g_R + (size_t)p * ((size_t)NB * HW * HW) + rowbase + P0 + q * 4),
               ov);
    }
}

// =====================================================================
// Pass 2: vertical (ky) fold + bias. 4 pixels per thread, float4 store.
// =====================================================================
__global__ void __launch_bounds__(256)
msd_pass2(const float* __restrict__ bias, float* __restrict__ out)
{
    int idx4 = blockIdx.x * 256 + threadIdx.x;
    int x4 = idx4 & 127;
    int y  = (idx4 >> 7) & 511;
    int t  = idx4 >> 16;
    int j  = t % 10;
    int b  = t / 10;
    int d  = j + 1;
    float bj = __ldg(bias + j);
    float a0 = bj, a1 = bj, a2 = bj, a3 = bj;
    #pragma unroll
    for (int ky = 0; ky < 3; ky++) {
        int y2 = y + (ky - 1) * d;
        if (y2 < 0 || y2 >= HW) continue;
        uint2 rv = __ldcs(reinterpret_cast<const uint2*>(
            g_R + (size_t)(j * 3 + ky) * ((size_t)NB * HW * HW)
                + ((size_t)b * HW + y2) * HW + (size_t)x4 * 4));
        float2 f0 = __half22float2(*reinterpret_cast<__half2*>(&rv.x));
        float2 f1 = __half22float2(*reinterpret_cast<__half2*>(&rv.y));
        a0 += f0.x; a1 += f0.y; a2 += f1.x; a3 += f1.y;
    }
    __stcs(reinterpret_cast<float4*>(
               out + ((size_t)(b * 42 + 32 + j) * HW + y) * HW + (size_t)x4 * 4),
           make_float4(a0, a1, a2, a3));
}

// =====================================================================
extern "C" void kernel_launch(void* const* d_in, const int* in_sizes, int n_in,
                              void* d_out, int out_size)
{
    const float* x = nullptr;
    const float* W = nullptr;
    const float* bias = nullptr;
    for (int i = 0; i < n_in; i++) {
        if (in_sizes[i] == 8 * 32 * 512 * 512) x    = (const float*)d_in[i];
        else if (in_sizes[i] == 2880)          W    = (const float*)d_in[i];
        else if (in_sizes[i] == 10)            bias = (const float*)d_in[i];
    }
    float* out = (float*)d_out;

    cudaFuncSetAttribute(msd_pass1,
                         cudaFuncAttributeMaxDynamicSharedMemorySize, SMEM_SIZE);

    dim3 g1(2, HW, NB);
    msd_pass1<<<g1, MTILE, SMEM_SIZE>>>(x, W, out);

    int n4 = NB * 10 * HW * HW / 4;          // 5,242,880 quads
    msd_pass2<<<n4 / 256, 256>>>(bias, out);
}

// round 12
// speedup vs baseline: 1.3255x; 1.0930x over previous
#include <cuda_runtime.h>
#include <cuda_bf16.h>
#include <cuda_fp16.h>
#include <cstdint>

#define HW 512
#define NB 8
#define NC 32

// R scratch: 30 planes [j*3+ky][b][y][x] fp16 = 126 MB
__device__ __half g_R[(size_t)30 * NB * HW * HW];
// Pre-decoded fp16 W operand: w[n][c], n = j*9+ky*3+kx (96 rows, 90 used)
__device__ __half g_Wh[96 * 32];

// ---------------- smem layout (pass 1) ----------------
// Tile = 256 output pixels, computed over 288-pixel range (16-px halo).
// Y tile : halfs, [96][296] at byte 0   (56832 B)
// A tile : halfs, [288][40] at byte 0   (23040 B, overlaps Y; all x-fragment
//          reads complete before Y is written). Row = 80 B: 4 data granules
//          of 16 B + 1 pad granule. Granule SWIZZLE: octet `oct` of row r
//          lives at slot (oct + (r>>3)) & 3   -> STS.128 at bank floor.
// W tile : halfs, [96][32]  at byte 56832 (6144 B)
#define MTILE 288
#define Y_STRIDE 296
#define W_OFF 56832
#define SMEM_SIZE 62976

__device__ __forceinline__ uint32_t smem_to_u32(const void* smem_ptr) {
    uint32_t addr;
    asm("{ .reg .u64 tmp; cvta.to.shared.u64 tmp, %1; cvt.u32.u64 %0, tmp; }"
        : "=r"(addr) : "l"(smem_ptr));
    return addr;
}

__device__ __forceinline__ void ldmatrix_x4(
    uint32_t& r0, uint32_t& r1, uint32_t& r2, uint32_t& r3, uint32_t addr)
{
    asm volatile(
        "ldmatrix.sync.aligned.m8n8.x4.shared.b16 {%0,%1,%2,%3}, [%4];"
        : "=r"(r0), "=r"(r1), "=r"(r2), "=r"(r3) : "r"(addr));
}

__device__ __forceinline__ void mma16816(
    float* d, const uint32_t* a, uint32_t b0, uint32_t b1)
{
    asm volatile(
        "mma.sync.aligned.m16n8k16.row.col.f32.f16.f16.f32 "
        "{%0,%1,%2,%3}, {%4,%5,%6,%7}, {%8,%9}, {%0,%1,%2,%3};"
        : "+f"(d[0]), "+f"(d[1]), "+f"(d[2]), "+f"(d[3])
        : "r"(a[0]), "r"(a[1]), "r"(a[2]), "r"(a[3]), "r"(b0), "r"(b1));
}

// Extract 4 consecutive halves starting at offset e (0..3) from 8 aligned
// halves held in w[0..3]. e must be warp-uniform (it is: e = (+-d)&3).
__device__ __forceinline__ void extract4(
    const uint32_t* w, int e, uint32_t& r0, uint32_t& r1)
{
    uint32_t a0 = (e & 2) ? w[1] : w[0];
    uint32_t a1 = (e & 2) ? w[2] : w[1];
    uint32_t a2 = (e & 2) ? w[3] : w[2];
    if (e & 1) {
        r0 = __funnelshift_r(a0, a1, 16);
        r1 = __funnelshift_r(a1, a2, 16);
    } else {
        r0 = a0;
        r1 = a1;
    }
}

// =====================================================================
// Prep: decode W [10][32][3][3] fp32 -> g_Wh[n][c] fp16 once per call.
// =====================================================================
__global__ void msd_prep(const float* __restrict__ W)
{
    int idx = blockIdx.x * 1024 + threadIdx.x;   // 0 .. 3071
    if (idx >= 96 * 32) return;
    int n = idx >> 5, c = idx & 31;
    float w = 0.0f;
    if (n < 90) {
        int j = n / 9, rem = n - j * 9;          // rem = ky*3+kx
        w = W[(j * 32 + c) * 9 + rem];
    }
    g_Wh[idx] = __float2half(w);
}

// =====================================================================
// Pass 1: one CTA per 256-pixel half-row. 288 threads = 9 warps, occ 3.
//   GEMM: D[n][m] = sum_k W[n][k] * x[m][k]  over 288-pixel halo range
//   Horizontal (kx) fold -> R[(j,ky)] fp16 for the 256 owned pixels.
//   Passthrough copy of x (channels 0..31) fused into the A fill.
// =====================================================================
__global__ void __launch_bounds__(288, 3)
msd_pass1(const float* __restrict__ x, const float* __restrict__ W,
          float* __restrict__ out)
{
    extern __shared__ char smem[];
    const uint32_t smem_base = smem_to_u32(smem);
    const int tid = threadIdx.x;
    const int wid = tid >> 5;
    const int lid = tid & 31;
    const int P0 = blockIdx.x * 256;      // first owned pixel
    const int y = blockIdx.y;
    const int b = blockIdx.z;

    __half* Ys = reinterpret_cast<__half*>(smem);

    // ---- fill W operand: straight vector copy of pre-decoded g_Wh ----
    {
        const uint4* src = reinterpret_cast<const uint4*>(g_Wh);
        uint4* dst = reinterpret_cast<uint4*>(smem + W_OFF);
        for (int idx = tid; idx < 384; idx += 288)   // 96*32 halfs = 384 uint4
            dst[idx] = src[idx];
    }

    // ---- fill A: thread = (pixel quad, channel octet); LDG/STG.128,
    //      swizzled STS.128 (bank floor); streaming stores ----
    const size_t xbase = (size_t)b * NC * HW * HW + (size_t)y * HW;
    const size_t obase = (size_t)b * 42 * HW * HW + (size_t)y * HW;
    {
        const int quad = tid % 72;         // 72 quads x 4 px = 288 px
        const int oct  = tid / 72;         // 4 octets x 8 ch = 32 ch
        const int lp0  = quad * 4;         // local pixel base
        const int gp0  = P0 - 16 + lp0;    // global pixel base (quad-aligned)
        const bool inimg = (gp0 >= 0) && (gp0 < HW);
        const bool owned = (lp0 >= 16) && (lp0 < 272);
        const int slot = (oct + (lp0 >> 3)) & 3;   // swizzled granule
        float v[8][4];
        #pragma unroll
        for (int c8 = 0; c8 < 8; c8++) {
            int c = oct * 8 + c8;
            float4 f = inimg
                ? *reinterpret_cast<const float4*>(
                      &x[xbase + (size_t)c * (HW * HW) + gp0])
                : make_float4(0.f, 0.f, 0.f, 0.f);
            v[c8][0] = f.x; v[c8][1] = f.y; v[c8][2] = f.z; v[c8][3] = f.w;
        }
        if (owned) {
            #pragma unroll
            for (int c8 = 0; c8 < 8; c8++) {
                int c = oct * 8 + c8;
                __stcs(reinterpret_cast<float4*>(
                           &out[obase + (size_t)c * (HW * HW) + gp0]),
                       make_float4(v[c8][0], v[c8][1], v[c8][2], v[c8][3]));
            }
        }
        #pragma unroll
        for (int i = 0; i < 4; i++) {
            __half2 h0 = __floats2half2_rn(v[0][i], v[1][i]);
            __half2 h1 = __floats2half2_rn(v[2][i], v[3][i]);
            __half2 h2 = __floats2half2_rn(v[4][i], v[5][i]);
            __half2 h3 = __floats2half2_rn(v[6][i], v[7][i]);
            *reinterpret_cast<uint4*>(smem + (lp0 + i) * 80 + slot * 16) =
                make_uint4(*reinterpret_cast<uint32_t*>(&h0),
                           *reinterpret_cast<uint32_t*>(&h1),
                           *reinterpret_cast<uint32_t*>(&h2),
                           *reinterpret_cast<uint32_t*>(&h3));
        }
    }
    __syncthreads();

    // ---- preload x (B operand) fragments: swizzle-aware LDS.32 pairs ----
    const int mb = wid * 32;
    const int g = lid >> 2, t = lid & 3;
    uint32_t bx[4][2][2];
    #pragma unroll
    for (int m8 = 0; m8 < 4; m8++)
        #pragma unroll
        for (int kh = 0; kh < 2; kh++) {
            int row = mb + m8 * 8 + g;
            int r3 = row >> 3;
            int gr0 = (2 * kh + r3) & 3;
            int gr1 = (2 * kh + 1 + r3) & 3;
            bx[m8][kh][0] = *reinterpret_cast<const uint32_t*>(
                smem + row * 80 + gr0 * 16 + 4 * t);
            bx[m8][kh][1] = *reinterpret_cast<const uint32_t*>(
                smem + row * 80 + gr1 * 16 + 4 * t);
        }
    __syncthreads();   // all x reads done -> Y may overwrite A region

    // ---- MMA: loop 6 n-tiles of 16; scatter half2 (conflict-free) ----
    const int r8 = lid & 7, t8 = lid >> 3;
    #pragma unroll
    for (int nt = 0; nt < 6; nt++) {
        const int n0 = nt * 16;
        uint32_t aw[2][4];
        #pragma unroll
        for (int kh = 0; kh < 2; kh++) {
            int row = n0 + r8 + (t8 & 1) * 8;
            int col = kh * 16 + (t8 >> 1) * 8;
            ldmatrix_x4(aw[kh][0], aw[kh][1], aw[kh][2], aw[kh][3],
                        smem_base + W_OFF + row * 64 + col * 2);
        }
        float acc[4][4];
        #pragma unroll
        for (int m8 = 0; m8 < 4; m8++) {
            #pragma unroll
            for (int i = 0; i < 4; i++) acc[m8][i] = 0.0f;
            #pragma unroll
            for (int kh = 0; kh < 2; kh++)
                mma16816(acc[m8], aw[kh], bx[m8][kh][0], bx[m8][kh][1]);
        }
        #pragma unroll
        for (int m8 = 0; m8 < 4; m8++) {
            int mcol = mb + m8 * 8 + 2 * t;
            __half2 lo = __floats2half2_rn(acc[m8][0], acc[m8][1]);
            __half2 hi = __floats2half2_rn(acc[m8][2], acc[m8][3]);
            *reinterpret_cast<__half2*>(&Ys[(n0 + g) * Y_STRIDE + mcol]) = lo;
            *reinterpret_cast<__half2*>(&Ys[(n0 + g + 8) * Y_STRIDE + mcol]) = hi;
        }
    }
    __syncthreads();

    // ---- horizontal (kx) fold -> R fp16; vector taps, HADD2 sums ----
    const size_t rowbase = ((size_t)b * HW + y) * HW;
    for (int idx = tid; idx < 30 * 64; idx += 288) {
        int p = idx >> 6;          // plane 0..29  (n = 3p)
        int q = idx & 63;          // quad within owned 256 pixels
        int j = (p * 11) >> 5;     // == p/3 for p < 30
        int n = 3 * p;
        int d = j + 1;
        int lm = q * 4 + 16;       // local pixel of quad start (lm % 4 == 0)

        uint2 cc = *reinterpret_cast<const uint2*>(&Ys[(n + 1) * Y_STRIDE + lm]);
        int el = (-d) & 3;
        int baseL = lm - d - el;
        uint32_t wl[4];
        {
            uint2 v0 = *reinterpret_cast<const uint2*>(&Ys[n * Y_STRIDE + baseL]);
            uint2 v1 = *reinterpret_cast<const uint2*>(&Ys[n * Y_STRIDE + baseL + 4]);
            wl[0] = v0.x; wl[1] = v0.y; wl[2] = v1.x; wl[3] = v1.y;
        }
        uint32_t l0, l1;
        extract4(wl, el, l0, l1);
        int er = d & 3;
        int baseR = lm + d - er;
        uint32_t wr[4];
        {
            uint2 v0 = *reinterpret_cast<const uint2*>(&Ys[(n + 2) * Y_STRIDE + baseR]);
            uint2 v1 = *reinterpret_cast<const uint2*>(&Ys[(n + 2) * Y_STRIDE + baseR + 4]);
            wr[0] = v0.x; wr[1] = v0.y; wr[2] = v1.x; wr[3] = v1.y;
        }
        uint32_t rr0, rr1;
        extract4(wr, er, rr0, rr1);

        __half2 o01 = __hadd2(__hadd2(*reinterpret_cast<__half2*>(&cc.x),
                                      *reinterpret_cast<__half2*>(&l0)),
                              *reinterpret_cast<__half2*>(&rr0));
        __half2 o23 = __hadd2(__hadd2(*reinterpret_cast<__half2*>(&cc.y),
                                      *reinterpret_cast<__half2*>(&l1)),
                              *reinterpret_cast<__half2*>(&rr1));
        uint2 ov = make_uint2(*reinterpret_cast<uint32_t*>(&o01),
                              *reinterpret_cast<uint32_t*>(&o23));
        __stcs(reinterpret_cast<uint2*>(
                   g_R + (size_t)p * ((size_t)NB * HW * HW) + rowbase + P0 + q * 4),
               ov);
    }
}

// =====================================================================
// Pass 2: vertical (ky) fold + bias. 4 pixels per thread, float4 store.
// =====================================================================
__global__ void __launch_bounds__(256)
msd_pass2(const float* __restrict__ bias, float* __restrict__ out)
{
    int idx4 = blockIdx.x * 256 + threadIdx.x;
    int x4 = idx4 & 127;
    int y  = (idx4 >> 7) & 511;
    int t  = idx4 >> 16;
    int j  = t % 10;
    int b  = t / 10;
    int d  = j + 1;
    float bj = __ldg(bias + j);
    float a0 = bj, a1 = bj, a2 = bj, a3 = bj;
    #pragma unroll
    for (int ky = 0; ky < 3; ky++) {
        int y2 = y + (ky - 1) * d;
        if (y2 < 0 || y2 >= HW) continue;
        uint2 rv = __ldcs(reinterpret_cast<const uint2*>(
            g_R + (size_t)(j * 3 + ky) * ((size_t)NB * HW * HW)
                + ((size_t)b * HW + y2) * HW + (size_t)x4 * 4));
        float2 f0 = __half22float2(*reinterpret_cast<__half2*>(&rv.x));
        float2 f1 = __half22float2(*reinterpret_cast<__half2*>(&rv.y));
        a0 += f0.x; a1 += f0.y; a2 += f1.x; a3 += f1.y;
    }
    __stcs(reinterpret_cast<float4*>(
               out + ((size_t)(b * 42 + 32 + j) * HW + y) * HW + (size_t)x4 * 4),
           make_float4(a0, a1, a2, a3));
}

// =====================================================================
extern "C" void kernel_launch(void* const* d_in, const int* in_sizes, int n_in,
                              void* d_out, int out_size)
{
    const float* x = nullptr;
    const float* W = nullptr;
    const float* bias = nullptr;
    for (int i = 0; i < n_in; i++) {
        if (in_sizes[i] == 8 * 32 * 512 * 512) x    = (const float*)d_in[i];
        else if (in_sizes[i] == 2880)          W    = (const float*)d_in[i];
        else if (in_sizes[i] == 10)            bias = (const float*)d_in[i];
    }
    float* out = (float*)d_out;

    cudaFuncSetAttribute(msd_pass1,
                         cudaFuncAttributeMaxDynamicSharedMemorySize, SMEM_SIZE);

    msd_prep<<<3, 1024>>>(W);

    dim3 g1(2, HW, NB);
    msd_pass1<<<g1, MTILE, SMEM_SIZE>>>(x, W, out);

    int n4 = NB * 10 * HW * HW / 4;          // 5,242,880 quads
    msd_pass2<<<n4 / 256, 256>>>(bias, out);
}

// round 13
// speedup vs baseline: 1.3896x; 1.0484x over previous
#include <cuda_runtime.h>
#include <cuda_bf16.h>
#include <cuda_fp16.h>
#include <cstdint>

#define HW 512
#define NB 8
#define NC 32

// R scratch: 30 planes [j*3+ky][b][y][x] fp16 = 126 MB
__device__ __half g_R[(size_t)30 * NB * HW * HW];
// Pre-decoded fp16 W operand: w[n][c], n = j*9+ky*3+kx (96 rows, 90 used)
__device__ __half g_Wh[96 * 32];

// ---------------- smem layout (pass 1) ----------------
// Tile = 256 output pixels over a 288-pixel halo range. GEMM N-split in two
// halves of 48 planes so Y is half-size -> occ 4.
// Y tile : halfs, [48][296] at byte 0   (28416 B)
// A tile : halfs, [288][40] at byte 0   (23040 B, overlaps Y; all x-fragment
//          reads complete before Y is written). Row = 80 B: 4 data granules
//          of 16 B + 1 pad granule, granule-swizzled (slot = (oct+(r>>3))&3).
// W tile : halfs, [96][32]  at byte 28416 (6144 B)
#define MTILE 288
#define Y_STRIDE 296
#define W_OFF 28416
#define SMEM_SIZE 34560

__device__ __forceinline__ uint32_t smem_to_u32(const void* smem_ptr) {
    uint32_t addr;
    asm("{ .reg .u64 tmp; cvta.to.shared.u64 tmp, %1; cvt.u32.u64 %0, tmp; }"
        : "=r"(addr) : "l"(smem_ptr));
    return addr;
}

__device__ __forceinline__ void ldmatrix_x4(
    uint32_t& r0, uint32_t& r1, uint32_t& r2, uint32_t& r3, uint32_t addr)
{
    asm volatile(
        "ldmatrix.sync.aligned.m8n8.x4.shared.b16 {%0,%1,%2,%3}, [%4];"
        : "=r"(r0), "=r"(r1), "=r"(r2), "=r"(r3) : "r"(addr));
}

__device__ __forceinline__ void mma16816(
    float* d, const uint32_t* a, uint32_t b0, uint32_t b1)
{
    asm volatile(
        "mma.sync.aligned.m16n8k16.row.col.f32.f16.f16.f32 "
        "{%0,%1,%2,%3}, {%4,%5,%6,%7}, {%8,%9}, {%0,%1,%2,%3};"
        : "+f"(d[0]), "+f"(d[1]), "+f"(d[2]), "+f"(d[3])
        : "r"(a[0]), "r"(a[1]), "r"(a[2]), "r"(a[3]), "r"(b0), "r"(b1));
}

// Extract 4 consecutive halves starting at offset e (0..3) from 8 aligned
// halves held in w[0..3]. e must be warp-uniform (it is: e = (+-d)&3).
__device__ __forceinline__ void extract4(
    const uint32_t* w, int e, uint32_t& r0, uint32_t& r1)
{
    uint32_t a0 = (e & 2) ? w[1] : w[0];
    uint32_t a1 = (e & 2) ? w[2] : w[1];
    uint32_t a2 = (e & 2) ? w[3] : w[2];
    if (e & 1) {
        r0 = __funnelshift_r(a0, a1, 16);
        r1 = __funnelshift_r(a1, a2, 16);
    } else {
        r0 = a0;
        r1 = a1;
    }
}

// =====================================================================
// Prep: decode W [10][32][3][3] fp32 -> g_Wh[n][c] fp16 once per call.
// =====================================================================
__global__ void msd_prep(const float* __restrict__ W)
{
    int idx = blockIdx.x * 1024 + threadIdx.x;   // 0 .. 3071
    if (idx >= 96 * 32) return;
    int n = idx >> 5, c = idx & 31;
    float w = 0.0f;
    if (n < 90) {
        int j = n / 9, rem = n - j * 9;          // rem = ky*3+kx
        w = W[(j * 32 + c) * 9 + rem];
    }
    g_Wh[idx] = __float2half(w);
}

// =====================================================================
// Pass 1: one CTA per 256-pixel half-row. 288 threads = 9 warps, occ 4.
//   GEMM: D[n][m] = sum_k W[n][k] * x[m][k]  over 288-pixel halo range,
//   issued in two N-halves of 48 planes (Y buffer reused).
//   Horizontal (kx) fold -> R[(j,ky)] fp16 for the 256 owned pixels.
//   Passthrough copy of x (channels 0..31) fused into the A fill.
// =====================================================================
__global__ void __launch_bounds__(288, 4)
msd_pass1(const float* __restrict__ x, const float* __restrict__ W,
          float* __restrict__ out)
{
    extern __shared__ char smem[];
    const uint32_t smem_base = smem_to_u32(smem);
    const int tid = threadIdx.x;
    const int wid = tid >> 5;
    const int lid = tid & 31;
    const int P0 = blockIdx.x * 256;      // first owned pixel
    const int y = blockIdx.y;
    const int b = blockIdx.z;

    __half* Ys = reinterpret_cast<__half*>(smem);

    // ---- fill W operand: straight vector copy of pre-decoded g_Wh ----
    {
        const uint4* src = reinterpret_cast<const uint4*>(g_Wh);
        uint4* dst = reinterpret_cast<uint4*>(smem + W_OFF);
        for (int idx = tid; idx < 384; idx += 288)   // 96*32 halfs = 384 uint4
            dst[idx] = src[idx];
    }

    // ---- fill A: thread = (pixel quad, channel octet); LDG/STG.128,
    //      swizzled STS.128 (bank floor); streaming stores ----
    const size_t xbase = (size_t)b * NC * HW * HW + (size_t)y * HW;
    const size_t obase = (size_t)b * 42 * HW * HW + (size_t)y * HW;
    {
        const int quad = tid % 72;         // 72 quads x 4 px = 288 px
        const int oct  = tid / 72;         // 4 octets x 8 ch = 32 ch
        const int lp0  = quad * 4;         // local pixel base
        const int gp0  = P0 - 16 + lp0;    // global pixel base (quad-aligned)
        const bool inimg = (gp0 >= 0) && (gp0 < HW);
        const bool owned = (lp0 >= 16) && (lp0 < 272);
        const int slot = (oct + (lp0 >> 3)) & 3;   // swizzled granule
        float v[8][4];
        #pragma unroll
        for (int c8 = 0; c8 < 8; c8++) {
            int c = oct * 8 + c8;
            float4 f = inimg
                ? *reinterpret_cast<const float4*>(
                      &x[xbase + (size_t)c * (HW * HW) + gp0])
                : make_float4(0.f, 0.f, 0.f, 0.f);
            v[c8][0] = f.x; v[c8][1] = f.y; v[c8][2] = f.z; v[c8][3] = f.w;
        }
        if (owned) {
            #pragma unroll
            for (int c8 = 0; c8 < 8; c8++) {
                int c = oct * 8 + c8;
                __stcs(reinterpret_cast<float4*>(
                           &out[obase + (size_t)c * (HW * HW) + gp0]),
                       make_float4(v[c8][0], v[c8][1], v[c8][2], v[c8][3]));
            }
        }
        #pragma unroll
        for (int i = 0; i < 4; i++) {
            __half2 h0 = __floats2half2_rn(v[0][i], v[1][i]);
            __half2 h1 = __floats2half2_rn(v[2][i], v[3][i]);
            __half2 h2 = __floats2half2_rn(v[4][i], v[5][i]);
            __half2 h3 = __floats2half2_rn(v[6][i], v[7][i]);
            *reinterpret_cast<uint4*>(smem + (lp0 + i) * 80 + slot * 16) =
                make_uint4(*reinterpret_cast<uint32_t*>(&h0),
                           *reinterpret_cast<uint32_t*>(&h1),
                           *reinterpret_cast<uint32_t*>(&h2),
                           *reinterpret_cast<uint32_t*>(&h3));
        }
    }
    __syncthreads();

    // ---- preload x (B operand) fragments: swizzle-aware LDS.32 pairs ----
    const int mb = wid * 32;
    const int g = lid >> 2, t = lid & 3;
    uint32_t bx[4][2][2];
    #pragma unroll
    for (int m8 = 0; m8 < 4; m8++)
        #pragma unroll
        for (int kh = 0; kh < 2; kh++) {
            int row = mb + m8 * 8 + g;
            int r3 = row >> 3;
            int gr0 = (2 * kh + r3) & 3;
            int gr1 = (2 * kh + 1 + r3) & 3;
            bx[m8][kh][0] = *reinterpret_cast<const uint32_t*>(
                smem + row * 80 + gr0 * 16 + 4 * t);
            bx[m8][kh][1] = *reinterpret_cast<const uint32_t*>(
                smem + row * 80 + gr1 * 16 + 4 * t);
        }
    __syncthreads();   // all x reads done -> Y may overwrite A region

    const int r8 = lid & 7, t8 = lid >> 3;
    const size_t rowbase = ((size_t)b * HW + y) * HW;

    // ==== two N-halves: MMA 48 planes -> fold 16/14 planes, Y reused ====
    #pragma unroll
    for (int h = 0; h < 2; h++) {
        // ---- MMA: 3 n-tiles of 16; scatter half2 (conflict-free) ----
        #pragma unroll
        for (int ntl = 0; ntl < 3; ntl++) {
            const int n0 = (h * 3 + ntl) * 16;     // global n base
            const int nl0 = ntl * 16;              // local Y row base
            uint32_t aw[2][4];
            #pragma unroll
            for (int kh = 0; kh < 2; kh++) {
                int row = n0 + r8 + (t8 & 1) * 8;
                int col = kh * 16 + (t8 >> 1) * 8;
                ldmatrix_x4(aw[kh][0], aw[kh][1], aw[kh][2], aw[kh][3],
                            smem_base + W_OFF + row * 64 + col * 2);
            }
            float acc[4][4];
            #pragma unroll
            for (int m8 = 0; m8 < 4; m8++) {
                #pragma unroll
                for (int i = 0; i < 4; i++) acc[m8][i] = 0.0f;
                #pragma unroll
                for (int kh = 0; kh < 2; kh++)
                    mma16816(acc[m8], aw[kh], bx[m8][kh][0], bx[m8][kh][1]);
            }
            #pragma unroll
            for (int m8 = 0; m8 < 4; m8++) {
                int mcol = mb + m8 * 8 + 2 * t;
                __half2 lo = __floats2half2_rn(acc[m8][0], acc[m8][1]);
                __half2 hi = __floats2half2_rn(acc[m8][2], acc[m8][3]);
                *reinterpret_cast<__half2*>(&Ys[(nl0 + g) * Y_STRIDE + mcol]) = lo;
                *reinterpret_cast<__half2*>(&Ys[(nl0 + g + 8) * Y_STRIDE + mcol]) = hi;
            }
        }
        __syncthreads();

        // ---- horizontal (kx) fold for this half's planes ----
        const int p0 = (h == 0) ? 0 : 16;
        const int np = (h == 0) ? 16 : 14;
        for (int idx = tid; idx < np * 64; idx += 288) {
            int p = p0 + (idx >> 6);   // plane (warp-uniform per iteration)
            int q = idx & 63;          // quad within owned 256 pixels
            int j = (p * 11) >> 5;     // == p/3 for p < 30
            int nl = 3 * p - 48 * h;   // local Y row of kx=0 tap
            int d = j + 1;
            int lm = q * 4 + 16;       // local pixel of quad start (lm%4==0)

            uint2 cc = *reinterpret_cast<const uint2*>(&Ys[(nl + 1) * Y_STRIDE + lm]);
            int el = (-d) & 3;
            int baseL = lm - d - el;
            uint32_t wl[4];
            {
                uint2 v0 = *reinterpret_cast<const uint2*>(&Ys[nl * Y_STRIDE + baseL]);
                uint2 v1 = *reinterpret_cast<const uint2*>(&Ys[nl * Y_STRIDE + baseL + 4]);
                wl[0] = v0.x; wl[1] = v0.y; wl[2] = v1.x; wl[3] = v1.y;
            }
            uint32_t l0, l1;
            extract4(wl, el, l0, l1);
            int er = d & 3;
            int baseR = lm + d - er;
            uint32_t wr[4];
            {
                uint2 v0 = *reinterpret_cast<const uint2*>(&Ys[(nl + 2) * Y_STRIDE + baseR]);
                uint2 v1 = *reinterpret_cast<const uint2*>(&Ys[(nl + 2) * Y_STRIDE + baseR + 4]);
                wr[0] = v0.x; wr[1] = v0.y; wr[2] = v1.x; wr[3] = v1.y;
            }
            uint32_t rr0, rr1;
            extract4(wr, er, rr0, rr1);

            __half2 o01 = __hadd2(__hadd2(*reinterpret_cast<__half2*>(&cc.x),
                                          *reinterpret_cast<__half2*>(&l0)),
                                  *reinterpret_cast<__half2*>(&rr0));
            __half2 o23 = __hadd2(__hadd2(*reinterpret_cast<__half2*>(&cc.y),
                                          *reinterpret_cast<__half2*>(&l1)),
                                  *reinterpret_cast<__half2*>(&rr1));
            uint2 ov = make_uint2(*reinterpret_cast<uint32_t*>(&o01),
                                  *reinterpret_cast<uint32_t*>(&o23));
            __stcs(reinterpret_cast<uint2*>(
                       g_R + (size_t)p * ((size_t)NB * HW * HW) + rowbase + P0 + q * 4),
                   ov);
        }
        __syncthreads();   // fold reads done before next half's scatter
    }
}

// =====================================================================
// Pass 2: vertical (ky) fold + bias. 4 pixels per thread, float4 store.
// =====================================================================
__global__ void __launch_bounds__(256)
msd_pass2(const float* __restrict__ bias, float* __restrict__ out)
{
    int idx4 = blockIdx.x * 256 + threadIdx.x;
    int x4 = idx4 & 127;
    int y  = (idx4 >> 7) & 511;
    int t  = idx4 >> 16;
    int j  = t % 10;
    int b  = t / 10;
    int d  = j + 1;
    float bj = __ldg(bias + j);
    float a0 = bj, a1 = bj, a2 = bj, a3 = bj;
    #pragma unroll
    for (int ky = 0; ky < 3; ky++) {
        int y2 = y + (ky - 1) * d;
        if (y2 < 0 || y2 >= HW) continue;
        uint2 rv = __ldcs(reinterpret_cast<const uint2*>(
            g_R + (size_t)(j * 3 + ky) * ((size_t)NB * HW * HW)
                + ((size_t)b * HW + y2) * HW + (size_t)x4 * 4));
        float2 f0 = __half22float2(*reinterpret_cast<__half2*>(&rv.x));
        float2 f1 = __half22float2(*reinterpret_cast<__half2*>(&rv.y));
        a0 += f0.x; a1 += f0.y; a2 += f1.x; a3 += f1.y;
    }
    __stcs(reinterpret_cast<float4*>(
               out + ((size_t)(b * 42 + 32 + j) * HW + y) * HW + (size_t)x4 * 4),
           make_float4(a0, a1, a2, a3));
}

// =====================================================================
extern "C" void kernel_launch(void* const* d_in, const int* in_sizes, int n_in,
                              void* d_out, int out_size)
{
    const float* x = nullptr;
    const float* W = nullptr;
    const float* bias = nullptr;
    for (int i = 0; i < n_in; i++) {
        if (in_sizes[i] == 8 * 32 * 512 * 512) x    = (const float*)d_in[i];
        else if (in_sizes[i] == 2880)          W    = (const float*)d_in[i];
        else if (in_sizes[i] == 10)            bias = (const float*)d_in[i];
    }
    float* out = (float*)d_out;

    cudaFuncSetAttribute(msd_pass1,
                         cudaFuncAttributeMaxDynamicSharedMemorySize, SMEM_SIZE);

    msd_prep<<<3, 1024>>>(W);

    dim3 g1(2, HW, NB);
    msd_pass1<<<g1, MTILE, SMEM_SIZE>>>(x, W, out);

    int n4 = NB * 10 * HW * HW / 4;          // 5,242,880 quads
    msd_pass2<<<n4 / 256, 256>>>(bias, out);
}

// round 14
// speedup vs baseline: 1.4423x; 1.0379x over previous
#include <cuda_runtime.h>
#include <cuda_bf16.h>
#include <cuda_fp16.h>
#include <cstdint>

#define HW 512
#define NB 8
#define NC 32

// R scratch: 30 planes [j*3+ky][b][y][x] fp16 = 126 MB
__device__ __half g_R[(size_t)30 * NB * HW * HW];
// Pre-decoded fp16 W operand: w[n][c], n = j*9+ky*3+kx (96 rows, 90 used)
__device__ __half g_Wh[96 * 32];

// ---------------- smem layout (pass 1) ----------------
// Tile = 256 output pixels over a 288-pixel halo range. GEMM N-split in two
// halves of 48 planes so Y is half-size -> occ 4.
// Y tile : halfs, [48][296] at byte 0   (28416 B)
// A tile : halfs, [288][40] at byte 0   (23040 B, overlaps Y; all x-fragment
//          reads complete before Y is written). Row = 80 B: 4 data granules
//          of 16 B + 1 pad granule, granule-swizzled (slot = (oct+(r>>3))&3).
// W tile : halfs, [96][32]  at byte 28416 (6144 B)
#define MTILE 288
#define Y_STRIDE 296
#define W_OFF 28416
#define SMEM_SIZE 34560

__device__ __forceinline__ uint32_t smem_to_u32(const void* smem_ptr) {
    uint32_t addr;
    asm("{ .reg .u64 tmp; cvta.to.shared.u64 tmp, %1; cvt.u32.u64 %0, tmp; }"
        : "=r"(addr) : "l"(smem_ptr));
    return addr;
}

__device__ __forceinline__ void ldmatrix_x4(
    uint32_t& r0, uint32_t& r1, uint32_t& r2, uint32_t& r3, uint32_t addr)
{
    asm volatile(
        "ldmatrix.sync.aligned.m8n8.x4.shared.b16 {%0,%1,%2,%3}, [%4];"
        : "=r"(r0), "=r"(r1), "=r"(r2), "=r"(r3) : "r"(addr));
}

__device__ __forceinline__ void mma16816(
    float* d, const uint32_t* a, uint32_t b0, uint32_t b1)
{
    asm volatile(
        "mma.sync.aligned.m16n8k16.row.col.f32.f16.f16.f32 "
        "{%0,%1,%2,%3}, {%4,%5,%6,%7}, {%8,%9}, {%0,%1,%2,%3};"
        : "+f"(d[0]), "+f"(d[1]), "+f"(d[2]), "+f"(d[3])
        : "r"(a[0]), "r"(a[1]), "r"(a[2]), "r"(a[3]), "r"(b0), "r"(b1));
}

// Extract 4 consecutive halves starting at offset e (0..3) from 8 aligned
// halves held in w[0..3]. e must be warp-uniform (it is: e = (+-d)&3).
__device__ __forceinline__ void extract4(
    const uint32_t* w, int e, uint32_t& r0, uint32_t& r1)
{
    uint32_t a0 = (e & 2) ? w[1] : w[0];
    uint32_t a1 = (e & 2) ? w[2] : w[1];
    uint32_t a2 = (e & 2) ? w[3] : w[2];
    if (e & 1) {
        r0 = __funnelshift_r(a0, a1, 16);
        r1 = __funnelshift_r(a1, a2, 16);
    } else {
        r0 = a0;
        r1 = a1;
    }
}

// =====================================================================
// Prep: decode W [10][32][3][3] fp32 -> g_Wh[n][c] fp16 once per call.
// =====================================================================
__global__ void msd_prep(const float* __restrict__ W)
{
    int idx = blockIdx.x * 1024 + threadIdx.x;   // 0 .. 3071
    if (idx >= 96 * 32) return;
    int n = idx >> 5, c = idx & 31;
    float w = 0.0f;
    if (n < 90) {
        int j = n / 9, rem = n - j * 9;          // rem = ky*3+kx
        w = W[(j * 32 + c) * 9 + rem];
    }
    g_Wh[idx] = __float2half(w);
}

// =====================================================================
// Pass 1: one CTA per 256-pixel half-row. 288 threads = 9 warps, occ 4.
//   GEMM: D[n][m] = sum_k W[n][k] * x[m][k]  over 288-pixel halo range,
//   issued in two N-halves of 48 planes (Y buffer reused).
//   Horizontal (kx) fold -> R[(j,ky)] fp16 for the 256 owned pixels.
//   Passthrough copy of x (channels 0..31) fused into the A fill.
//   L2 policy: x read-once (ldcs), out write-once (stcs), R default
//   (KEEP in L2 for pass2 -- R is 126 MB == L2 capacity, read-once later).
// =====================================================================
__global__ void __launch_bounds__(288, 4)
msd_pass1(const float* __restrict__ x, const float* __restrict__ W,
          float* __restrict__ out)
{
    extern __shared__ char smem[];
    const uint32_t smem_base = smem_to_u32(smem);
    const int tid = threadIdx.x;
    const int wid = tid >> 5;
    const int lid = tid & 31;
    const int P0 = blockIdx.x * 256;      // first owned pixel
    const int y = blockIdx.y;
    const int b = blockIdx.z;

    __half* Ys = reinterpret_cast<__half*>(smem);

    // ---- fill W operand: straight vector copy of pre-decoded g_Wh ----
    {
        const uint4* src = reinterpret_cast<const uint4*>(g_Wh);
        uint4* dst = reinterpret_cast<uint4*>(smem + W_OFF);
        for (int idx = tid; idx < 384; idx += 288)   // 96*32 halfs = 384 uint4
            dst[idx] = src[idx];
    }

    // ---- fill A: thread = (pixel quad, channel octet); LDG/STG.128,
    //      swizzled STS.128 (bank floor) ----
    const size_t xbase = (size_t)b * NC * HW * HW + (size_t)y * HW;
    const size_t obase = (size_t)b * 42 * HW * HW + (size_t)y * HW;
    {
        const int quad = tid % 72;         // 72 quads x 4 px = 288 px
        const int oct  = tid / 72;         // 4 octets x 8 ch = 32 ch
        const int lp0  = quad * 4;         // local pixel base
        const int gp0  = P0 - 16 + lp0;    // global pixel base (quad-aligned)
        const bool inimg = (gp0 >= 0) && (gp0 < HW);
        const bool owned = (lp0 >= 16) && (lp0 < 272);
        const int slot = (oct + (lp0 >> 3)) & 3;   // swizzled granule
        float v[8][4];
        #pragma unroll
        for (int c8 = 0; c8 < 8; c8++) {
            int c = oct * 8 + c8;
            float4 f = inimg
                ? __ldcs(reinterpret_cast<const float4*>(
                      &x[xbase + (size_t)c * (HW * HW) + gp0]))
                : make_float4(0.f, 0.f, 0.f, 0.f);
            v[c8][0] = f.x; v[c8][1] = f.y; v[c8][2] = f.z; v[c8][3] = f.w;
        }
        if (owned) {
            #pragma unroll
            for (int c8 = 0; c8 < 8; c8++) {
                int c = oct * 8 + c8;
                __stcs(reinterpret_cast<float4*>(
                           &out[obase + (size_t)c * (HW * HW) + gp0]),
                       make_float4(v[c8][0], v[c8][1], v[c8][2], v[c8][3]));
            }
        }
        #pragma unroll
        for (int i = 0; i < 4; i++) {
            __half2 h0 = __floats2half2_rn(v[0][i], v[1][i]);
            __half2 h1 = __floats2half2_rn(v[2][i], v[3][i]);
            __half2 h2 = __floats2half2_rn(v[4][i], v[5][i]);
            __half2 h3 = __floats2half2_rn(v[6][i], v[7][i]);
            *reinterpret_cast<uint4*>(smem + (lp0 + i) * 80 + slot * 16) =
                make_uint4(*reinterpret_cast<uint32_t*>(&h0),
                           *reinterpret_cast<uint32_t*>(&h1),
                           *reinterpret_cast<uint32_t*>(&h2),
                           *reinterpret_cast<uint32_t*>(&h3));
        }
    }
    __syncthreads();

    // ---- preload x (B operand) fragments: swizzle-aware LDS.32 pairs ----
    const int mb = wid * 32;
    const int g = lid >> 2, t = lid & 3;
    uint32_t bx[4][2][2];
    #pragma unroll
    for (int m8 = 0; m8 < 4; m8++)
        #pragma unroll
        for (int kh = 0; kh < 2; kh++) {
            int row = mb + m8 * 8 + g;
            int r3 = row >> 3;
            int gr0 = (2 * kh + r3) & 3;
            int gr1 = (2 * kh + 1 + r3) & 3;
            bx[m8][kh][0] = *reinterpret_cast<const uint32_t*>(
                smem + row * 80 + gr0 * 16 + 4 * t);
            bx[m8][kh][1] = *reinterpret_cast<const uint32_t*>(
                smem + row * 80 + gr1 * 16 + 4 * t);
        }
    __syncthreads();   // all x reads done -> Y may overwrite A region

    const int r8 = lid & 7, t8 = lid >> 3;
    const size_t rowbase = ((size_t)b * HW + y) * HW;

    // ==== two N-halves: MMA 48 planes -> fold 16/14 planes, Y reused ====
    #pragma unroll
    for (int h = 0; h < 2; h++) {
        // ---- MMA: 3 n-tiles of 16; scatter half2 (conflict-free) ----
        #pragma unroll
        for (int ntl = 0; ntl < 3; ntl++) {
            const int n0 = (h * 3 + ntl) * 16;     // global n base
            const int nl0 = ntl * 16;              // local Y row base
            uint32_t aw[2][4];
            #pragma unroll
            for (int kh = 0; kh < 2; kh++) {
                int row = n0 + r8 + (t8 & 1) * 8;
                int col = kh * 16 + (t8 >> 1) * 8;
                ldmatrix_x4(aw[kh][0], aw[kh][1], aw[kh][2], aw[kh][3],
                            smem_base + W_OFF + row * 64 + col * 2);
            }
            float acc[4][4];
            #pragma unroll
            for (int m8 = 0; m8 < 4; m8++) {
                #pragma unroll
                for (int i = 0; i < 4; i++) acc[m8][i] = 0.0f;
                #pragma unroll
                for (int kh = 0; kh < 2; kh++)
                    mma16816(acc[m8], aw[kh], bx[m8][kh][0], bx[m8][kh][1]);
            }
            #pragma unroll
            for (int m8 = 0; m8 < 4; m8++) {
                int mcol = mb + m8 * 8 + 2 * t;
                __half2 lo = __floats2half2_rn(acc[m8][0], acc[m8][1]);
                __half2 hi = __floats2half2_rn(acc[m8][2], acc[m8][3]);
                *reinterpret_cast<__half2*>(&Ys[(nl0 + g) * Y_STRIDE + mcol]) = lo;
                *reinterpret_cast<__half2*>(&Ys[(nl0 + g + 8) * Y_STRIDE + mcol]) = hi;
            }
        }
        __syncthreads();

        // ---- horizontal (kx) fold for this half's planes ----
        const int p0 = (h == 0) ? 0 : 16;
        const int np = (h == 0) ? 16 : 14;
        for (int idx = tid; idx < np * 64; idx += 288) {
            int p = p0 + (idx >> 6);   // plane (warp-uniform per iteration)
            int q = idx & 63;          // quad within owned 256 pixels
            int j = (p * 11) >> 5;     // == p/3 for p < 30
            int nl = 3 * p - 48 * h;   // local Y row of kx=0 tap
            int d = j + 1;
            int lm = q * 4 + 16;       // local pixel of quad start (lm%4==0)

            uint2 cc = *reinterpret_cast<const uint2*>(&Ys[(nl + 1) * Y_STRIDE + lm]);
            int el = (-d) & 3;
            int baseL = lm - d - el;
            uint32_t wl[4];
            {
                uint2 v0 = *reinterpret_cast<const uint2*>(&Ys[nl * Y_STRIDE + baseL]);
                uint2 v1 = *reinterpret_cast<const uint2*>(&Ys[nl * Y_STRIDE + baseL + 4]);
                wl[0] = v0.x; wl[1] = v0.y; wl[2] = v1.x; wl[3] = v1.y;
            }
            uint32_t l0, l1;
            extract4(wl, el, l0, l1);
            int er = d & 3;
            int baseR = lm + d - er;
            uint32_t wr[4];
            {
                uint2 v0 = *reinterpret_cast<const uint2*>(&Ys[(nl + 2) * Y_STRIDE + baseR]);
                uint2 v1 = *reinterpret_cast<const uint2*>(&Ys[(nl + 2) * Y_STRIDE + baseR + 4]);
                wr[0] = v0.x; wr[1] = v0.y; wr[2] = v1.x; wr[3] = v1.y;
            }
            uint32_t rr0, rr1;
            extract4(wr, er, rr0, rr1);

            __half2 o01 = __hadd2(__hadd2(*reinterpret_cast<__half2*>(&cc.x),
                                          *reinterpret_cast<__half2*>(&l0)),
                                  *reinterpret_cast<__half2*>(&rr0));
            __half2 o23 = __hadd2(__hadd2(*reinterpret_cast<__half2*>(&cc.y),
                                          *reinterpret_cast<__half2*>(&l1)),
                                  *reinterpret_cast<__half2*>(&rr1));
            // default policy: keep R resident in L2 for pass2
            *reinterpret_cast<uint2*>(
                g_R + (size_t)p * ((size_t)NB * HW * HW) + rowbase + P0 + q * 4) =
                make_uint2(*reinterpret_cast<uint32_t*>(&o01),
                           *reinterpret_cast<uint32_t*>(&o23));
        }
        __syncthreads();   // fold reads done before next half's scatter
    }
}

// =====================================================================
// Pass 2: vertical (ky) fold + bias. 8 pixels per thread, LDG/STG.128.
// =====================================================================
__global__ void __launch_bounds__(256)
msd_pass2(const float* __restrict__ bias, float* __restrict__ out)
{
    int idx8 = blockIdx.x * 256 + threadIdx.x;
    int x8 = idx8 & 63;
    int y  = (idx8 >> 6) & 511;
    int t  = idx8 >> 15;
    int j  = t % 10;
    int b  = t / 10;
    int d  = j + 1;
    float bj = __ldg(bias + j);
    float a[8];
    #pragma unroll
    for (int i = 0; i < 8; i++) a[i] = bj;
    #pragma unroll
    for (int ky = 0; ky < 3; ky++) {
        int y2 = y + (ky - 1) * d;
        if (y2 < 0 || y2 >= HW) continue;
        uint4 rv = __ldcs(reinterpret_cast<const uint4*>(
            g_R + (size_t)(j * 3 + ky) * ((size_t)NB * HW * HW)
                + ((size_t)b * HW + y2) * HW + (size_t)x8 * 8));
        const uint32_t* rp = reinterpret_cast<const uint32_t*>(&rv);
        #pragma unroll
        for (int k = 0; k < 4; k++) {
            float2 f = __half22float2(*reinterpret_cast<const __half2*>(&rp[k]));
            a[2 * k]     += f.x;
            a[2 * k + 1] += f.y;
        }
    }
    float* obase = out + ((size_t)(b * 42 + 32 + j) * HW + y) * HW + (size_t)x8 * 8;
    __stcs(reinterpret_cast<float4*>(obase),
           make_float4(a[0], a[1], a[2], a[3]));
    __stcs(reinterpret_cast<float4*>(obase + 4),
           make_float4(a[4], a[5], a[6], a[7]));
}

// =====================================================================
extern "C" void kernel_launch(void* const* d_in, const int* in_sizes, int n_in,
                              void* d_out, int out_size)
{
    const float* x = nullptr;
    const float* W = nullptr;
    const float* bias = nullptr;
    for (int i = 0; i < n_in; i++) {
        if (in_sizes[i] == 8 * 32 * 512 * 512) x    = (const float*)d_in[i];
        else if (in_sizes[i] == 2880)          W    = (const float*)d_in[i];
        else if (in_sizes[i] == 10)            bias = (const float*)d_in[i];
    }
    float* out = (float*)d_out;

    cudaFuncSetAttribute(msd_pass1,
                         cudaFuncAttributeMaxDynamicSharedMemorySize, SMEM_SIZE);

    msd_prep<<<3, 1024>>>(W);

    dim3 g1(2, HW, NB);
    msd_pass1<<<g1, MTILE, SMEM_SIZE>>>(x, W, out);

    int n8 = NB * 10 * HW * HW / 8;          // 2,621,440 octets
    msd_pass2<<<n8 / 256, 256>>>(bias, out);
}